// round 1
// baseline (speedup 1.0000x reference)
#include <cuda_runtime.h>
#include <math.h>

#define Bsz 8
#define Cc 64
#define HWd 128
#define NPIX (HWd*HWd)          // 16384
#define PLANE ((size_t)Cc*NPIX) // per-batch plane of a 64-ch tensor
#define BS ((size_t)Bsz*Cc*NPIX)
#define LEAKv 0.2f
#define CLAMPv 0.8f
#define EPSv 1e-5f

#define TW 16
#define TH 8
#define OCB 32
#define ICCH 16
#define CWS (64*64*9)

// ---------------- scratch (device globals; no allocation) ----------------
__device__ float g_x1[Bsz*Cc*NPIX];
__device__ float g_x2[Bsz*Cc*NPIX];
__device__ float g_y1[Bsz*Cc*NPIX];
__device__ float g_y2[Bsz*Cc*NPIX];
__device__ float g_rb[Bsz*Cc*NPIX];
__device__ float g_sb[Bsz*Cc*NPIX];
__device__ float g_xf[Bsz*Cc*NPIX];
__device__ float g_hb[Bsz*Cc*NPIX];
__device__ float g_gv[Bsz*Cc];
__device__ int   g_sel[Bsz*2];
__device__ float g_cofsel[Bsz*2];

// ---------------- 3x3 conv, direct, fp32 ----------------
// MODE 0: out = conv+bias
// MODE 1: out = conv+bias+add1+add2                       (y1)
// MODE 2: out = conv+bias+add1                            (s_pre)
// MODE 3: out = conv+bias+add1 + add2*exp(clamp*(2sig(spre)-1))  (y2)
// MODE 4: out = lrelu(conv+bias[e])                       (expert conv1, indirect)
// MODE 5: out (+)= cof * (conv+bias[e]+add1)              (expert conv2, indirect)
#define FMA_OC4(wv, a0, a1, a2, a3) \
    acc[0][0] += wv.x * a0; acc[0][1] += wv.x * a1; acc[0][2] += wv.x * a2; acc[0][3] += wv.x * a3; \
    acc[1][0] += wv.y * a0; acc[1][1] += wv.y * a1; acc[1][2] += wv.y * a2; acc[1][3] += wv.y * a3; \
    acc[2][0] += wv.z * a0; acc[2][1] += wv.z * a1; acc[2][2] += wv.z * a2; acc[2][3] += wv.z * a3; \
    acc[3][0] += wv.w * a0; acc[3][1] += wv.w * a1; acc[3][2] += wv.w * a2; acc[3][3] += wv.w * a3;

template<int MODE>
__global__ __launch_bounds__(256)
void conv3x3_k(const float* __restrict__ in, const float* __restrict__ wts,
               const float* __restrict__ bias, float* __restrict__ out,
               const float* __restrict__ add1, const float* __restrict__ add2,
               const float* __restrict__ spre,
               const int* __restrict__ sel, const float* __restrict__ cofsel,
               int slot, int accum)
{
    __shared__ float s_in[ICCH][TH+2][TW+2];
    __shared__ float s_w[ICCH][9][OCB];

    int tid = threadIdx.x;
    int bz = blockIdx.z;
    int b = bz >> 1;
    int oc0 = (bz & 1) * OCB;
    int w0 = blockIdx.x * TW;
    int h0 = blockIdx.y * TH;

    const float* wbase = wts;
    const float* bbase = bias;
    float cw = 1.f;
    if (MODE == 4 || MODE == 5) {
        int e = sel[b*2 + slot];
        wbase = wts + (size_t)e * (Cc*Cc*9);
        bbase = bias + e * Cc;
        if (MODE == 5) cw = cofsel[b*2 + slot];
    }

    const float* inb = in + (size_t)b * PLANE;

    int ocg = tid & 7;
    int pg  = tid >> 3;
    int ph  = pg >> 2;
    int pw4 = (pg & 3) * 4;
    int ocl0 = ocg * 4;

    float acc[4][4];
    #pragma unroll
    for (int i = 0; i < 4; i++)
        #pragma unroll
        for (int j = 0; j < 4; j++) acc[i][j] = 0.f;

    for (int ch = 0; ch < Cc; ch += ICCH) {
        for (int i = tid; i < ICCH*(TH+2)*(TW+2); i += 256) {
            int ic  = i / ((TH+2)*(TW+2));
            int rem = i % ((TH+2)*(TW+2));
            int rr = rem / (TW+2);
            int cc = rem % (TW+2);
            int h = h0 - 1 + rr;
            int w = w0 - 1 + cc;
            float v = 0.f;
            if ((unsigned)h < HWd && (unsigned)w < HWd)
                v = inb[(size_t)(ch+ic)*NPIX + h*HWd + w];
            s_in[ic][rr][cc] = v;
        }
        for (int i = tid; i < ICCH*9*OCB; i += 256) {
            int ocl = i & (OCB-1);
            int k = (i / OCB) % 9;
            int ic = i / (OCB*9);
            s_w[ic][k][ocl] = wbase[((size_t)(oc0+ocl)*Cc + (ch+ic))*9 + k];
        }
        __syncthreads();
        #pragma unroll 1
        for (int ic = 0; ic < ICCH; ic++) {
            const float* rbase = &s_in[ic][ph][pw4];
            const float* wb = &s_w[ic][0][ocl0];
            #pragma unroll
            for (int ky = 0; ky < 3; ky++) {
                const float* rr = rbase + ky*(TW+2);
                float v0 = rr[0], v1 = rr[1], v2 = rr[2], v3 = rr[3], v4 = rr[4], v5 = rr[5];
                float4 w0v = *(const float4*)(wb + (ky*3+0)*OCB);
                float4 w1v = *(const float4*)(wb + (ky*3+1)*OCB);
                float4 w2v = *(const float4*)(wb + (ky*3+2)*OCB);
                FMA_OC4(w0v, v0, v1, v2, v3);
                FMA_OC4(w1v, v1, v2, v3, v4);
                FMA_OC4(w2v, v2, v3, v4, v5);
            }
        }
        __syncthreads();
    }

    int h = h0 + ph;
    #pragma unroll
    for (int i = 0; i < 4; i++) {
        int oc = oc0 + ocl0 + i;
        float bv = bbase[oc];
        size_t base = (size_t)b*PLANE + (size_t)oc*NPIX + (size_t)h*HWd + w0 + pw4;
        #pragma unroll
        for (int j = 0; j < 4; j++) {
            size_t idx = base + j;
            float v = acc[i][j] + bv;
            if (MODE == 1) {
                v += add1[idx] + add2[idx];
            } else if (MODE == 2) {
                v += add1[idx];
            } else if (MODE == 3) {
                float sp = spre[idx];
                float sig = 1.f / (1.f + expf(-sp));
                float s = CLAMPv * (2.f*sig - 1.f);
                v += add1[idx] + add2[idx] * expf(s);
            } else if (MODE == 4) {
                v = v > 0.f ? v : LEAKv * v;
            } else if (MODE == 5) {
                v = (v + add1[idx]) * cw;
                if (accum) v += out[idx];
            }
            out[idx] = v;
        }
    }
}

// ---------------- 1x1 GEMM (winv / fuse) ----------------
template<int IC>
__global__ __launch_bounds__(256)
void gemm1x1_k(const float* __restrict__ inA, const float* __restrict__ inB,
               const float* __restrict__ W, const float* __restrict__ bias,
               float* __restrict__ outA, float* __restrict__ outB)
{
    __shared__ float s_x[16][128];
    __shared__ float s_w[16][32];
    int tid = threadIdx.x;
    int b = blockIdx.z;
    int oc0 = blockIdx.y * 32;
    int p0 = blockIdx.x * 128;
    int ocl0 = (tid & 7) * 4;
    int pp0 = (tid >> 3) * 4;

    float acc[4][4];
    #pragma unroll
    for (int i = 0; i < 4; i++)
        #pragma unroll
        for (int j = 0; j < 4; j++) acc[i][j] = 0.f;

    for (int ch = 0; ch < IC; ch += 16) {
        #pragma unroll
        for (int t = 0; t < 8; t++) {
            int i = tid + t*256;
            int ic = i >> 7, p = i & 127;
            int icg = ch + ic;
            float v;
            if (inB != nullptr) {
                const float* src = (icg < 64) ? inA : inB;
                int icl = icg & 63;
                v = src[(size_t)b*PLANE + (size_t)icl*NPIX + p0 + p];
            } else {
                v = inA[((size_t)b*IC + icg)*NPIX + p0 + p];
            }
            s_x[ic][p] = v;
        }
        #pragma unroll
        for (int t = 0; t < 2; t++) {
            int i = tid + t*256;
            int ic = i >> 5, ocl = i & 31;
            s_w[ic][ocl] = W[(size_t)(oc0+ocl)*IC + ch + ic];
        }
        __syncthreads();
        #pragma unroll
        for (int ic = 0; ic < 16; ic++) {
            float4 wv = *(const float4*)&s_w[ic][ocl0];
            float x0 = s_x[ic][pp0+0], x1 = s_x[ic][pp0+1];
            float x2 = s_x[ic][pp0+2], x3 = s_x[ic][pp0+3];
            FMA_OC4(wv, x0, x1, x2, x3);
        }
        __syncthreads();
    }

    #pragma unroll
    for (int i = 0; i < 4; i++) {
        int oc = oc0 + ocl0 + i;
        float bv = bias ? bias[oc] : 0.f;
        float* dst = outA;
        int ocd = oc;
        if (outB != nullptr && oc >= 64) { dst = outB; ocd = oc - 64; }
        size_t base = (size_t)b*PLANE + (size_t)ocd*NPIX + p0 + pp0;
        #pragma unroll
        for (int j = 0; j < 4; j++)
            dst[base + j] = acc[i][j] + bv;
    }
}

// ---------------- instance norm (in-place, first 32 channels) ----------------
__global__ __launch_bounds__(256)
void inorm_k(float* __restrict__ r, const float* __restrict__ nw, const float* __restrict__ nb)
{
    int bidx = blockIdx.x;
    int b = bidx >> 5, c = bidx & 31;
    float* p = r + (size_t)b*PLANE + (size_t)c*NPIX;
    int tid = threadIdx.x;
    float s = 0.f, s2 = 0.f;
    for (int i = tid; i < NPIX; i += 256) { float v = p[i]; s += v; s2 += v*v; }
    __shared__ float sh[256], sh2[256];
    sh[tid] = s; sh2[tid] = s2;
    __syncthreads();
    for (int st = 128; st; st >>= 1) {
        if (tid < st) { sh[tid] += sh[tid+st]; sh2[tid] += sh2[tid+st]; }
        __syncthreads();
    }
    float mean = sh[0] * (1.f/NPIX);
    float var = sh2[0] * (1.f/NPIX) - mean*mean;
    float inv = rsqrtf(var + EPSv);
    float ga = nw[c], be = nb[c];
    for (int i = tid; i < NPIX; i += 256)
        p[i] = (p[i] - mean) * inv * ga + be;
}

// ---------------- global max+mean pool ----------------
__global__ __launch_bounds__(256)
void pool_k(const float* __restrict__ xf, float* __restrict__ g)
{
    int bc = blockIdx.x;
    const float* p = xf + (size_t)bc * NPIX;
    int tid = threadIdx.x;
    float mx = -1e30f, sm = 0.f;
    for (int i = tid; i < NPIX; i += 256) { float v = p[i]; mx = fmaxf(mx, v); sm += v; }
    __shared__ float smx[256], ssm[256];
    smx[tid] = mx; ssm[tid] = sm;
    __syncthreads();
    for (int st = 128; st; st >>= 1) {
        if (tid < st) { smx[tid] = fmaxf(smx[tid], smx[tid+st]); ssm[tid] += ssm[tid+st]; }
        __syncthreads();
    }
    if (tid == 0) g[bc] = smx[0] + ssm[0] * (1.f/NPIX);
}

// ---------------- gating ----------------
__global__ void gate_k(const float* __restrict__ g,
                       const float* __restrict__ gw0, const float* __restrict__ gb0,
                       const float* __restrict__ gw1, const float* __restrict__ gb1,
                       float* __restrict__ cof_out, int* __restrict__ sel,
                       float* __restrict__ cofsel)
{
    int b = threadIdx.x;
    if (b >= Bsz) return;
    float lg[4], noi[4];
    for (int e = 0; e < 4; e++) {
        float a0 = gb0[e], a1 = gb1[e];
        for (int c = 0; c < 64; c++) {
            float gv = g[b*64 + c];
            a0 += gw0[e*64 + c] * gv;
            a1 += gw1[e*64 + c] * gv;
        }
        lg[e] = a1 > 0.f ? a1 : LEAKv * a1;
        noi[e] = fmaxf(a0, 0.f) + log1pf(expf(-fabsf(a0)));   // stable softplus
    }
    float m = 0.25f * (noi[0] + noi[1] + noi[2] + noi[3]);
    float var = 0.f;
    for (int e = 0; e < 4; e++) { float d = noi[e] - m; var += d*d; }
    float sd = sqrtf(var / 3.f);   // ddof=1
    float sc[4];
    for (int e = 0; e < 4; e++) sc[e] = lg[e] + (noi[e] - m) / sd;
    int i0 = 0;
    for (int e = 1; e < 4; e++) if (sc[e] > sc[i0]) i0 = e;
    int i1 = -1;
    for (int e = 0; e < 4; e++) {
        if (e == i0) continue;
        if (i1 < 0 || sc[e] > sc[i1]) i1 = e;
    }
    float mm = fmaxf(lg[i0], lg[i1]);
    float e0 = expf(lg[i0] - mm), e1 = expf(lg[i1] - mm);
    float c0 = e0 / (e0 + e1), c1 = e1 / (e0 + e1);
    if (cof_out) {
        for (int e = 0; e < 4; e++) cof_out[b*4 + e] = 0.f;
        cof_out[b*4 + i0] = c0;
        cof_out[b*4 + i1] = c1;
    }
    sel[b*2 + 0] = i0; sel[b*2 + 1] = i1;
    cofsel[b*2 + 0] = c0; cofsel[b*2 + 1] = c1;
}

// ---------------- launch ----------------
extern "C" void kernel_launch(void* const* d_in, const int* in_sizes, int n_in,
                              void* d_out, int out_size)
{
    const float* x       = (const float*)d_in[0];
    const float* winv    = (const float*)d_in[1];
    const float* blk_w1  = (const float*)d_in[2];
    const float* blk_b1  = (const float*)d_in[3];
    const float* blk_nw  = (const float*)d_in[4];
    const float* blk_nb  = (const float*)d_in[5];
    const float* blk_w2  = (const float*)d_in[6];
    const float* blk_b2  = (const float*)d_in[7];
    const float* fuse_w  = (const float*)d_in[8];
    const float* fuse_b  = (const float*)d_in[9];
    const float* gw0     = (const float*)d_in[10];
    const float* gb0     = (const float*)d_in[11];
    const float* gw1     = (const float*)d_in[12];
    const float* gb1     = (const float*)d_in[13];
    const float* ew1     = (const float*)d_in[14];
    const float* eb1     = (const float*)d_in[15];
    const float* ew2     = (const float*)d_in[16];
    const float* eb2     = (const float*)d_in[17];
    float* out = (float*)d_out;
    float* cof_out = ((size_t)out_size >= BS + Bsz*4) ? out + BS : nullptr;

    float *x1, *x2, *y1, *y2, *rb, *sb, *xf, *hb, *gv, *cofsel; int* sel;
    void* p;
    cudaGetSymbolAddress(&p, g_x1);  x1 = (float*)p;
    cudaGetSymbolAddress(&p, g_x2);  x2 = (float*)p;
    cudaGetSymbolAddress(&p, g_y1);  y1 = (float*)p;
    cudaGetSymbolAddress(&p, g_y2);  y2 = (float*)p;
    cudaGetSymbolAddress(&p, g_rb);  rb = (float*)p;
    cudaGetSymbolAddress(&p, g_sb);  sb = (float*)p;
    cudaGetSymbolAddress(&p, g_xf);  xf = (float*)p;
    cudaGetSymbolAddress(&p, g_hb);  hb = (float*)p;
    cudaGetSymbolAddress(&p, g_gv);  gv = (float*)p;
    cudaGetSymbolAddress(&p, g_sel); sel = (int*)p;
    cudaGetSymbolAddress(&p, g_cofsel); cofsel = (float*)p;

    dim3 cgrid(HWd/TW, HWd/TH, Bsz*2);
    dim3 wgrid(NPIX/128, 4, Bsz);   // winv: OC=128 -> 4 oc-blocks
    dim3 fgrid(NPIX/128, 2, Bsz);   // fuse: OC=64  -> 2 oc-blocks

    // z = winv @ x, split into x1 (oc<64) and x2
    gemm1x1_k<128><<<wgrid, 256>>>(x, nullptr, winv, nullptr, x1, x2);

    // hin0(x2) -> y1 = x1 + x2 + conv2(...)
    conv3x3_k<0><<<cgrid, 256>>>(x2, blk_w1 + 0*CWS, blk_b1 + 0*64, rb,
                                 nullptr, nullptr, nullptr, nullptr, nullptr, 0, 0);
    inorm_k<<<Bsz*32, 256>>>(rb, blk_nw + 0*32, blk_nb + 0*32);
    conv3x3_k<1><<<cgrid, 256>>>(rb, blk_w2 + 0*CWS, blk_b2 + 0*64, y1,
                                 x2, x1, nullptr, nullptr, nullptr, 0, 0);

    // hin2(y1) -> s_pre = y1 + conv2(...)
    conv3x3_k<0><<<cgrid, 256>>>(y1, blk_w1 + 2*CWS, blk_b1 + 2*64, rb,
                                 nullptr, nullptr, nullptr, nullptr, nullptr, 0, 0);
    inorm_k<<<Bsz*32, 256>>>(rb, blk_nw + 2*32, blk_nb + 2*32);
    conv3x3_k<2><<<cgrid, 256>>>(rb, blk_w2 + 2*CWS, blk_b2 + 2*64, sb,
                                 y1, nullptr, nullptr, nullptr, nullptr, 0, 0);

    // hin1(y1) fused with flow: y2 = x2*exp(clamp*(2sig(s_pre)-1)) + y1 + conv2(...)
    conv3x3_k<0><<<cgrid, 256>>>(y1, blk_w1 + 1*CWS, blk_b1 + 1*64, rb,
                                 nullptr, nullptr, nullptr, nullptr, nullptr, 0, 0);
    inorm_k<<<Bsz*32, 256>>>(rb, blk_nw + 1*32, blk_nb + 1*32);
    conv3x3_k<3><<<cgrid, 256>>>(rb, blk_w2 + 1*CWS, blk_b2 + 1*64, y2,
                                 y1, x2, sb, nullptr, nullptr, 0, 0);

    // fuse conv1x1 on concat(y1, y2)
    gemm1x1_k<128><<<fgrid, 256>>>(y1, y2, fuse_w, fuse_b, xf, nullptr);

    // gating
    pool_k<<<Bsz*64, 256>>>(xf, gv);
    gate_k<<<1, 32>>>(gv, gw0, gb0, gw1, gb1, cof_out, sel, cofsel);

    // experts (only the K=2 selected per batch, via device-side indirection)
    for (int slot = 0; slot < 2; slot++) {
        conv3x3_k<4><<<cgrid, 256>>>(xf, ew1, eb1, hb,
                                     nullptr, nullptr, nullptr, sel, cofsel, slot, 0);
        conv3x3_k<5><<<cgrid, 256>>>(hb, ew2, eb2, out,
                                     xf, nullptr, nullptr, sel, cofsel, slot, slot);
    }
}